// round 1
// baseline (speedup 1.0000x reference)
#include <cuda_runtime.h>

#define W 512
#define H 512
#define PLANES 48            // 16 batch * 3 channels
#define TILE 32
#define HALO 5
#define IN_TILE 42           // TILE + 2*HALO

__device__ double g_accum;

__global__ void ssim_zero_accum() { g_accum = 0.0; }

__global__ void ssim_finalize(float* out) {
    out[0] = (float)(g_accum / ((double)PLANES * (double)W * (double)H));
}

__launch_bounds__(256)
__global__ void ssim_main(const float* __restrict__ img1,
                          const float* __restrict__ img2) {
    // raw input tiles (stride padded to 44 to decouple rows)
    __shared__ float sX[IN_TILE][IN_TILE + 2];
    __shared__ float sY[IN_TILE][IN_TILE + 2];
    // horizontal-pass intermediates: 42 rows x 32 cols (stride 33)
    __shared__ float hx [IN_TILE][TILE + 1];
    __shared__ float hy [IN_TILE][TILE + 1];
    __shared__ float hxx[IN_TILE][TILE + 1];
    __shared__ float hyy[IN_TILE][TILE + 1];
    __shared__ float hxy[IN_TILE][TILE + 1];
    __shared__ float wsum[8];

    const int tid  = threadIdx.x;
    const int plane = blockIdx.z;
    const int row0 = blockIdx.y * TILE;
    const int col0 = blockIdx.x * TILE;
    const float* p1 = img1 + (size_t)plane * W * H;
    const float* p2 = img2 + (size_t)plane * W * H;

    // Gaussian window (sigma=1.5, K=11). Hardcoded exp(-d^2/4.5) values,
    // renormalized in float so the weights sum to exactly ~1.
    float g[11];
    {
        const float e0 = 0.00386590f;  // exp(-25/4.5)
        const float e1 = 0.02856550f;  // exp(-16/4.5)
        const float e2 = 0.13533528f;  // exp(-9/4.5) = exp(-2)
        const float e3 = 0.41111229f;  // exp(-4/4.5)
        const float e4 = 0.80073740f;  // exp(-1/4.5)
        const float e5 = 1.0f;
        float s = e5 + 2.0f * (e0 + e1 + e2 + e3 + e4);
        float inv = 1.0f / s;
        g[0] = g[10] = e0 * inv;
        g[1] = g[9]  = e1 * inv;
        g[2] = g[8]  = e2 * inv;
        g[3] = g[7]  = e3 * inv;
        g[4] = g[6]  = e4 * inv;
        g[5] = e5 * inv;
    }

    // Phase 1: load 42x42 haloed tiles (zero pad outside image)
    for (int idx = tid; idx < IN_TILE * IN_TILE; idx += 256) {
        int r = idx / IN_TILE, c = idx - r * IN_TILE;
        int gr = row0 + r - HALO, gc = col0 + c - HALO;
        bool ok = (gr >= 0) & (gr < H) & (gc >= 0) & (gc < W);
        float xv = 0.f, yv = 0.f;
        if (ok) {
            int off = gr * W + gc;
            xv = p1[off];
            yv = p2[off];
        }
        sX[r][c] = xv;
        sY[r][c] = yv;
    }
    __syncthreads();

    // Phase 2: horizontal pass over 42 rows x 32 output cols
    for (int idx = tid; idx < IN_TILE * TILE; idx += 256) {
        int r = idx / TILE, c = idx - r * TILE;
        float sx = 0.f, sy = 0.f, sxx = 0.f, syy = 0.f, sxy = 0.f;
#pragma unroll
        for (int k = 0; k < 11; k++) {
            float xv = sX[r][c + k];
            float yv = sY[r][c + k];
            float w = g[k];
            sx  += w * xv;
            sy  += w * yv;
            sxx += w * xv * xv;
            syy += w * yv * yv;
            sxy += w * xv * yv;
        }
        hx [r][c] = sx;
        hy [r][c] = sy;
        hxx[r][c] = sxx;
        hyy[r][c] = syy;
        hxy[r][c] = sxy;
    }
    __syncthreads();

    // Phase 3: vertical pass + SSIM map + thread-local sum
    float local = 0.f;
    for (int idx = tid; idx < TILE * TILE; idx += 256) {
        int r = idx / TILE, c = idx - r * TILE;
        float mu1 = 0.f, mu2 = 0.f, vxx = 0.f, vyy = 0.f, vxy = 0.f;
#pragma unroll
        for (int k = 0; k < 11; k++) {
            float w = g[k];
            mu1 += w * hx [r + k][c];
            mu2 += w * hy [r + k][c];
            vxx += w * hxx[r + k][c];
            vyy += w * hyy[r + k][c];
            vxy += w * hxy[r + k][c];
        }
        float mu1sq = mu1 * mu1;
        float mu2sq = mu2 * mu2;
        float mu12  = mu1 * mu2;
        float s1  = vxx - mu1sq;
        float s2  = vyy - mu2sq;
        float s12 = vxy - mu12;
        const float C1 = 1e-4f;
        const float C2 = 9e-4f;
        float v1 = 2.f * s12 + C2;
        float v2 = s1 + s2 + C2 + 1e-6f;
        local += (2.f * mu12 + C1) * v1 / ((mu1sq + mu2sq + C1) * v2);
    }

    // Block reduction -> double atomic
#pragma unroll
    for (int off = 16; off > 0; off >>= 1)
        local += __shfl_down_sync(0xffffffffu, local, off);
    if ((tid & 31) == 0) wsum[tid >> 5] = local;
    __syncthreads();
    if (tid < 8) {
        float v = wsum[tid];
#pragma unroll
        for (int off = 4; off > 0; off >>= 1)
            v += __shfl_down_sync(0xffu, v, off);
        if (tid == 0) atomicAdd(&g_accum, (double)v);
    }
}

extern "C" void kernel_launch(void* const* d_in, const int* in_sizes, int n_in,
                              void* d_out, int out_size) {
    const float* img1 = (const float*)d_in[0];
    const float* img2 = (const float*)d_in[1];
    float* out = (float*)d_out;

    ssim_zero_accum<<<1, 1>>>();
    dim3 grid(W / TILE, H / TILE, PLANES);
    ssim_main<<<grid, 256>>>(img1, img2);
    ssim_finalize<<<1, 1>>>(out);
}

// round 2
// speedup vs baseline: 1.7823x; 1.7823x over previous
#include <cuda_runtime.h>

#define W 512
#define H 512
#define PLANES 48
#define TX 64          // output tile width
#define TY 32          // output tile height
#define VST 76         // vh row stride (floats); 74 columns used
#define NTH 320

__device__ double g_accum;
__device__ unsigned int g_count;

// Gaussian taps exp(-d^2/4.5), d=0..5 (double), normalized at compile time.
#define E0d 1.0
#define E1d 0.8007374029168081
#define E2d 0.4111122905071874
#define E3d 0.1353352832366127
#define E4d 0.0285655007845531
#define E5d 0.0038659201394728
#define ESd (E0d + 2.0*(E1d+E2d+E3d+E4d+E5d))
#define GW0 ((float)(E5d/ESd))
#define GW1 ((float)(E4d/ESd))
#define GW2 ((float)(E3d/ESd))
#define GW3 ((float)(E2d/ESd))
#define GW4 ((float)(E1d/ESd))
#define GW5 ((float)(E0d/ESd))

__launch_bounds__(NTH, 2)
__global__ void ssim_fused(const float* __restrict__ img1,
                           const float* __restrict__ img2,
                           float* __restrict__ out) {
    // vertical-pass intermediates: [quantity][row][col] ; 5*32*76*4 = 48640 B
    __shared__ float vh[5][TY][VST];
    __shared__ float wpart[NTH / 32];

    const float gw[11] = {GW0, GW1, GW2, GW3, GW4, GW5, GW4, GW3, GW2, GW1, GW0};

    const int tid   = threadIdx.x;
    const int plane = blockIdx.z;
    const int row0  = blockIdx.y * TY;
    const int col0  = blockIdx.x * TX;
    const float* p1 = img1 + (size_t)plane * (W * H);
    const float* p2 = img2 + (size_t)plane * (W * H);

    // ---------------- Phase A: vertical 11-tap conv, registers only ----------
    // 304 strips = 76 columns x 4 groups of 8 output rows. Direct coalesced LDG.
    if (tid < 4 * VST) {
        const int gi = tid / VST;          // row group 0..3
        const int cc = tid - gi * VST;     // smem column 0..75
        const int gc = col0 + cc - 5;      // global column
        const bool colOk = (gc >= 0) && (gc < W);
        const int rbase = row0 + gi * 8 - 5;

        float aX[8], aY[8], aXX[8], aYY[8], aXY[8];
#pragma unroll
        for (int i = 0; i < 8; i++) { aX[i]=0.f; aY[i]=0.f; aXX[i]=0.f; aYY[i]=0.f; aXY[i]=0.f; }

#pragma unroll
        for (int j = 0; j < 18; j++) {
            const int gr = rbase + j;
            float x = 0.f, y = 0.f;
            if (colOk && gr >= 0 && gr < H) {
                x = p1[gr * W + gc];
                y = p2[gr * W + gc];
            }
            const float xx = x * x, yy = y * y, xy = x * y;
#pragma unroll
            for (int i = 0; i < 8; i++) {
                const int k = j - i;               // tap index, compile-time
                if (k >= 0 && k < 11) {
                    const float wv = gw[k];
                    aX [i] += wv * x;
                    aY [i] += wv * y;
                    aXX[i] += wv * xx;
                    aYY[i] += wv * yy;
                    aXY[i] += wv * xy;
                }
            }
        }
        const int r0 = gi * 8;
#pragma unroll
        for (int i = 0; i < 8; i++) {
            vh[0][r0 + i][cc] = aX [i];
            vh[1][r0 + i][cc] = aY [i];
            vh[2][r0 + i][cc] = aXX[i];
            vh[3][r0 + i][cc] = aYY[i];
            vh[4][r0 + i][cc] = aXY[i];
        }
    }
    __syncthreads();

    // ---------------- Phase B: horizontal 11-tap conv + SSIM -----------------
    // 256 strips: 32 rows x 8 column-groups of 8 outputs each.
    float local = 0.f;
    if (tid < 256) {
        const int r  = tid & 31;
        const int c0 = (tid >> 5) * 8;     // output col within tile (window starts at cc=c0)

        float m[5][8];
#pragma unroll
        for (int q = 0; q < 5; q++) {
            // 18-wide window starting at cc=c0 (16B aligned, stride 304B -> conflict-free LDS.128)
            float f[20];
            const float4* rp = reinterpret_cast<const float4*>(&vh[q][r][c0]);
#pragma unroll
            for (int v = 0; v < 5; v++) {
                float4 t = rp[v];
                f[4*v+0] = t.x; f[4*v+1] = t.y; f[4*v+2] = t.z; f[4*v+3] = t.w;
            }
#pragma unroll
            for (int i = 0; i < 8; i++) {
                float s = 0.f;
#pragma unroll
                for (int k = 0; k < 11; k++)
                    s += gw[k] * f[i + k];
                m[q][i] = s;
            }
        }

        const float C1 = 1e-4f;
        const float C2 = 9e-4f;
#pragma unroll
        for (int i = 0; i < 8; i++) {
            const float mu1 = m[0][i], mu2 = m[1][i];
            const float mu1sq = mu1 * mu1;
            const float mu2sq = mu2 * mu2;
            const float mu12  = mu1 * mu2;
            const float s1  = m[2][i] - mu1sq;
            const float s2  = m[3][i] - mu2sq;
            const float s12 = m[4][i] - mu12;
            const float num = (2.f * mu12 + C1) * (2.f * s12 + C2);
            const float den = (mu1sq + mu2sq + C1) * (s1 + s2 + C2 + 1e-6f);
            local += __fdividef(num, den);
        }
    }

    // ---------------- Reduction: warp shuffle -> block -> device -------------
#pragma unroll
    for (int off = 16; off > 0; off >>= 1)
        local += __shfl_down_sync(0xffffffffu, local, off);
    if ((tid & 31) == 0) wpart[tid >> 5] = local;
    __syncthreads();
    if (tid == 0) {
        float bs = 0.f;
#pragma unroll
        for (int wv = 0; wv < NTH / 32; wv++) bs += wpart[wv];
        atomicAdd(&g_accum, (double)bs);
        __threadfence();
        const unsigned total = gridDim.x * gridDim.y * gridDim.z;
        if (atomicAdd(&g_count, 1u) == total - 1) {
            const double acc = atomicAdd(&g_accum, 0.0);
            out[0] = (float)(acc / ((double)PLANES * (double)W * (double)H));
            g_accum = 0.0;   // reset for next (deterministic) replay
            g_count = 0u;
        }
    }
}

extern "C" void kernel_launch(void* const* d_in, const int* in_sizes, int n_in,
                              void* d_out, int out_size) {
    const float* img1 = (const float*)d_in[0];
    const float* img2 = (const float*)d_in[1];
    float* out = (float*)d_out;

    dim3 grid(W / TX, H / TY, PLANES);
    ssim_fused<<<grid, NTH>>>(img1, img2, out);
}

// round 3
// speedup vs baseline: 1.8969x; 1.0643x over previous
#include <cuda_runtime.h>

#define W 512
#define H 512
#define PLANES 48
#define TX 64          // output tile width
#define TY 32          // output tile height
#define HALO 5
#define NCOL 74        // TX + 2*HALO columns of intermediates
#define PSTRIDE 74     // float2 stride (148 words ≡ 20 mod 32 -> conflict-free 16B loads)
#define CSTRIDE 76     // float stride  (76 ≡ 12 mod 32 -> conflict-free 16B loads)
#define NTH 320

typedef unsigned long long u64;

__device__ double g_accum;
__device__ unsigned int g_count;

// Gaussian taps exp(-d^2/4.5), normalized in double at compile time.
#define E0d 1.0
#define E1d 0.8007374029168081
#define E2d 0.4111122905071874
#define E3d 0.1353352832366127
#define E4d 0.0285655007845531
#define E5d 0.0038659201394728
#define ESd (E0d + 2.0*(E1d+E2d+E3d+E4d+E5d))
#define GW0 ((float)(E5d/ESd))
#define GW1 ((float)(E4d/ESd))
#define GW2 ((float)(E3d/ESd))
#define GW3 ((float)(E2d/ESd))
#define GW4 ((float)(E1d/ESd))
#define GW5 ((float)(E0d/ESd))

__device__ __forceinline__ u64 pack2(float a, float b) {
    u64 r; asm("mov.b64 %0, {%1, %2};" : "=l"(r) : "f"(a), "f"(b)); return r;
}
__device__ __forceinline__ void unpack2(u64 v, float& a, float& b) {
    asm("mov.b64 {%0, %1}, %2;" : "=f"(a), "=f"(b) : "l"(v));
}
__device__ __forceinline__ u64 fma2(u64 a, u64 b, u64 c) {
    u64 d; asm("fma.rn.f32x2 %0, %1, %2, %3;" : "=l"(d) : "l"(a), "l"(b), "l"(c)); return d;
}
__device__ __forceinline__ u64 mul2(u64 a, u64 b) {
    u64 d; asm("mul.rn.f32x2 %0, %1, %2;" : "=l"(d) : "l"(a), "l"(b)); return d;
}

// Vertical pass: each thread handles one column strip, 8 output rows,
// 18 input rows, registers only. Packed (x,y) and (x2,y2) chains + scalar xy.
template<bool GUARD>
__device__ __forceinline__ void phaseA(const float* __restrict__ p1,
                                       const float* __restrict__ p2,
                                       int row0, int col0, int tid,
                                       u64 (*vhV)[PSTRIDE], u64 (*vhS)[PSTRIDE],
                                       float (*vhC)[CSTRIDE],
                                       const float* gw, const u64* gw2) {
    const int gi = tid / NCOL;          // row group 0..3
    const int cc = tid - gi * NCOL;     // column 0..73
    const int gc = col0 + cc - HALO;
    const int rbase = row0 + gi * 8 - HALO;
    const bool colOk = !GUARD || ((unsigned)gc < (unsigned)W);

    u64 aV[8], aS[8];
    float aC[8];
#pragma unroll
    for (int i = 0; i < 8; i++) { aV[i] = 0ull; aS[i] = 0ull; aC[i] = 0.f; }

#pragma unroll
    for (int j = 0; j < 18; j++) {
        const int gr = rbase + j;
        float x = 0.f, y = 0.f;
        if (!GUARD || (colOk && (unsigned)gr < (unsigned)H)) {
            const int off = gr * W + gc;
            x = p1[off];
            y = p2[off];
        }
        const u64 v  = pack2(x, y);
        const u64 sq = mul2(v, v);
        const float cr = x * y;
#pragma unroll
        for (int i = 0; i < 8; i++) {
            const int k = j - i;        // compile-time tap index
            if (k >= 0 && k < 11) {
                aV[i] = fma2(gw2[k], v,  aV[i]);
                aS[i] = fma2(gw2[k], sq, aS[i]);
                aC[i] += gw[k] * cr;
            }
        }
    }
    const int r0 = gi * 8;
#pragma unroll
    for (int i = 0; i < 8; i++) {
        vhV[r0 + i][cc] = aV[i];
        vhS[r0 + i][cc] = aS[i];
        vhC[r0 + i][cc] = aC[i];
    }
}

__launch_bounds__(NTH, 2)
__global__ void ssim_fused(const float* __restrict__ img1,
                           const float* __restrict__ img2,
                           float* __restrict__ out) {
    __shared__ __align__(16) u64   vhV[TY][PSTRIDE];   // (hx, hy)    18944 B
    __shared__ __align__(16) u64   vhS[TY][PSTRIDE];   // (hxx, hyy)  18944 B
    __shared__ __align__(16) float vhC[TY][CSTRIDE];   // hxy          9728 B
    __shared__ float wpart[NTH / 32];

    const float gw[11] = {GW0, GW1, GW2, GW3, GW4, GW5, GW4, GW3, GW2, GW1, GW0};
    u64 gw2[11];
#pragma unroll
    for (int k = 0; k < 11; k++) gw2[k] = pack2(gw[k], gw[k]);

    const int tid   = threadIdx.x;
    const int plane = blockIdx.z;
    const int row0  = blockIdx.y * TY;
    const int col0  = blockIdx.x * TX;
    const float* p1 = img1 + (size_t)plane * (W * H);
    const float* p2 = img2 + (size_t)plane * (W * H);

    // ---------------- Phase A: vertical pass --------------------------------
    if (tid < 4 * NCOL) {
        const bool interior = (row0 >= HALO) && (row0 + TY + HALO <= H) &&
                              (col0 >= HALO) && (col0 + TX + HALO <= W);
        if (interior)
            phaseA<false>(p1, p2, row0, col0, tid, vhV, vhS, vhC, gw, gw2);
        else
            phaseA<true >(p1, p2, row0, col0, tid, vhV, vhS, vhC, gw, gw2);
    }
    __syncthreads();

    // ---------------- Phase B: horizontal pass + SSIM -----------------------
    float local = 0.f;
    if (tid < 256) {
        const int r  = tid & 31;
        const int c0 = (tid >> 5) * 8;   // output col group (even -> 16B aligned)

        // packed windows: 18 float2 = 9x 16B loads each
        u64 fV[18], fS[18];
        {
            const ulonglong2* rp = reinterpret_cast<const ulonglong2*>(&vhV[r][c0]);
#pragma unroll
            for (int v = 0; v < 9; v++) { ulonglong2 t = rp[v]; fV[2*v] = t.x; fV[2*v+1] = t.y; }
        }
        {
            const ulonglong2* rp = reinterpret_cast<const ulonglong2*>(&vhS[r][c0]);
#pragma unroll
            for (int v = 0; v < 9; v++) { ulonglong2 t = rp[v]; fS[2*v] = t.x; fS[2*v+1] = t.y; }
        }
        float fC[20];
        {
            const float4* rp = reinterpret_cast<const float4*>(&vhC[r][c0]);
#pragma unroll
            for (int v = 0; v < 5; v++) {
                float4 t = rp[v];
                fC[4*v+0] = t.x; fC[4*v+1] = t.y; fC[4*v+2] = t.z; fC[4*v+3] = t.w;
            }
        }

        const float C1 = 1e-4f;
        const float C2 = 9e-4f;
#pragma unroll
        for (int i = 0; i < 8; i++) {
            u64 mV = 0ull, mS = 0ull;
            float mC = 0.f;
#pragma unroll
            for (int k = 0; k < 11; k++) {
                mV = fma2(gw2[k], fV[i + k], mV);
                mS = fma2(gw2[k], fS[i + k], mS);
                mC += gw[k] * fC[i + k];
            }
            float mu1, mu2, vxx, vyy;
            unpack2(mV, mu1, mu2);
            unpack2(mS, vxx, vyy);
            const float mu1sq = mu1 * mu1;
            const float mu2sq = mu2 * mu2;
            const float mu12  = mu1 * mu2;
            const float s1  = vxx - mu1sq;
            const float s2  = vyy - mu2sq;
            const float s12 = mC  - mu12;
            const float num = (2.f * mu12 + C1) * (2.f * s12 + C2);
            const float den = (mu1sq + mu2sq + C1) * (s1 + s2 + C2 + 1e-6f);
            local += __fdividef(num, den);
        }
    }

    // ---------------- Reduction ----------------------------------------------
#pragma unroll
    for (int off = 16; off > 0; off >>= 1)
        local += __shfl_down_sync(0xffffffffu, local, off);
    if ((tid & 31) == 0) wpart[tid >> 5] = local;
    __syncthreads();
    if (tid == 0) {
        float bs = 0.f;
#pragma unroll
        for (int wv = 0; wv < NTH / 32; wv++) bs += wpart[wv];
        atomicAdd(&g_accum, (double)bs);
        __threadfence();
        const unsigned total = gridDim.x * gridDim.y * gridDim.z;
        if (atomicAdd(&g_count, 1u) == total - 1) {
            const double acc = atomicAdd(&g_accum, 0.0);
            out[0] = (float)(acc / ((double)PLANES * (double)W * (double)H));
            g_accum = 0.0;   // reset so every graph replay is identical
            g_count = 0u;
        }
    }
}

extern "C" void kernel_launch(void* const* d_in, const int* in_sizes, int n_in,
                              void* d_out, int out_size) {
    const float* img1 = (const float*)d_in[0];
    const float* img2 = (const float*)d_in[1];
    float* out = (float*)d_out;

    dim3 grid(W / TX, H / TY, PLANES);
    ssim_fused<<<grid, NTH>>>(img1, img2, out);
}

// round 4
// speedup vs baseline: 2.1437x; 1.1301x over previous
#include <cuda_runtime.h>

#define W 512
#define H 512
#define PLANES 48
#define TX 64          // output tile width
#define TY 32          // output tile height
#define HALO 5
#define NCOL 74        // TX + 2*HALO columns of intermediates
#define PSTRIDE 74     // float2 stride (148 words ≡ 20 mod 32 -> conflict-free 16B loads)
#define CSTRIDE 76     // float stride  (76 ≡ 12 mod 32 -> conflict-free 16B loads)
#define NTH 320

typedef unsigned long long u64;

__device__ double g_accum;
__device__ unsigned int g_count;

// Gaussian taps exp(-d^2/4.5), normalized in double at compile time.
#define E0d 1.0
#define E1d 0.8007374029168081
#define E2d 0.4111122905071874
#define E3d 0.1353352832366127
#define E4d 0.0285655007845531
#define E5d 0.0038659201394728
#define ESd (E0d + 2.0*(E1d+E2d+E3d+E4d+E5d))
#define GW0 ((float)(E5d/ESd))
#define GW1 ((float)(E4d/ESd))
#define GW2 ((float)(E3d/ESd))
#define GW3 ((float)(E2d/ESd))
#define GW4 ((float)(E1d/ESd))
#define GW5 ((float)(E0d/ESd))

__device__ __forceinline__ u64 pack2(float a, float b) {
    u64 r; asm("mov.b64 %0, {%1, %2};" : "=l"(r) : "f"(a), "f"(b)); return r;
}
__device__ __forceinline__ void unpack2(u64 v, float& a, float& b) {
    asm("mov.b64 {%0, %1}, %2;" : "=f"(a), "=f"(b) : "l"(v));
}
__device__ __forceinline__ u64 fma2(u64 a, u64 b, u64 c) {
    u64 d; asm("fma.rn.f32x2 %0, %1, %2, %3;" : "=l"(d) : "l"(a), "l"(b), "l"(c)); return d;
}
__device__ __forceinline__ u64 mul2(u64 a, u64 b) {
    u64 d; asm("mul.rn.f32x2 %0, %1, %2;" : "=l"(d) : "l"(a), "l"(b)); return d;
}

// Vertical pass: one column strip per thread, 8 output rows from 18 input
// rows, all in registers. Packed (x,y) and (x2,y2) chains + scalar xy.
template<bool GUARD>
__device__ __forceinline__ void phaseA(const float* __restrict__ p1,
                                       const float* __restrict__ p2,
                                       int row0, int col0, int tid,
                                       u64 (*vhV)[PSTRIDE], u64 (*vhS)[PSTRIDE],
                                       float (*vhC)[CSTRIDE],
                                       const float* gw, const u64* gw2) {
    const int gi = tid / NCOL;          // row group 0..3
    const int cc = tid - gi * NCOL;     // column 0..73
    const int gc = col0 + cc - HALO;
    const int rbase = row0 + gi * 8 - HALO;
    const bool colOk = !GUARD || ((unsigned)gc < (unsigned)W);

    u64 aV[8], aS[8];
    float aC[8];
#pragma unroll
    for (int i = 0; i < 8; i++) { aV[i] = 0ull; aS[i] = 0ull; aC[i] = 0.f; }

#pragma unroll
    for (int j = 0; j < 18; j++) {
        const int gr = rbase + j;
        float x = 0.f, y = 0.f;
        if (!GUARD || (colOk && (unsigned)gr < (unsigned)H)) {
            const int off = gr * W + gc;
            x = p1[off];
            y = p2[off];
        }
        const u64 v  = pack2(x, y);
        const u64 sq = mul2(v, v);
        const float cr = x * y;
#pragma unroll
        for (int i = 0; i < 8; i++) {
            const int k = j - i;        // compile-time tap index
            if (k >= 0 && k < 11) {
                const int ks = (k < 11 - 1 - k) ? k : (10 - k);  // symmetric tap
                aV[i] = fma2(gw2[ks], v,  aV[i]);
                aS[i] = fma2(gw2[ks], sq, aS[i]);
                aC[i] += gw[ks] * cr;
            }
        }
    }
    const int r0 = gi * 8;
#pragma unroll
    for (int i = 0; i < 8; i++) {
        vhV[r0 + i][cc] = aV[i];
        vhS[r0 + i][cc] = aS[i];
        vhC[r0 + i][cc] = aC[i];
    }
}

__launch_bounds__(NTH, 3)
__global__ void ssim_fused(const float* __restrict__ img1,
                           const float* __restrict__ img2,
                           float* __restrict__ out) {
    __shared__ __align__(16) u64   vhV[TY][PSTRIDE];   // (hx, hy)    18944 B
    __shared__ __align__(16) u64   vhS[TY][PSTRIDE];   // (hxx, hyy)  18944 B
    __shared__ __align__(16) float vhC[TY][CSTRIDE];   // hxy          9728 B
    __shared__ float wpart[NTH / 32];

    // only 6 distinct taps kept live (symmetry)
    const float gw[6] = {GW0, GW1, GW2, GW3, GW4, GW5};
    u64 gw2[6];
#pragma unroll
    for (int k = 0; k < 6; k++) gw2[k] = pack2(gw[k], gw[k]);

    const int tid   = threadIdx.x;
    const int plane = blockIdx.z;
    const int row0  = blockIdx.y * TY;
    const int col0  = blockIdx.x * TX;
    const float* p1 = img1 + (size_t)plane * (W * H);
    const float* p2 = img2 + (size_t)plane * (W * H);

    // ---------------- Phase A: vertical pass --------------------------------
    if (tid < 4 * NCOL) {
        const bool interior = (row0 >= HALO) && (row0 + TY + HALO <= H) &&
                              (col0 >= HALO) && (col0 + TX + HALO <= W);
        if (interior)
            phaseA<false>(p1, p2, row0, col0, tid, vhV, vhS, vhC, gw, gw2);
        else
            phaseA<true >(p1, p2, row0, col0, tid, vhV, vhS, vhC, gw, gw2);
    }
    __syncthreads();

    // ---------------- Phase B: horizontal pass + SSIM -----------------------
    float local = 0.f;
    if (tid < 256) {
        const int r  = tid & 31;
        const int c0 = (tid >> 5) * 8;   // output col group (even -> 16B aligned)

        // packed windows: 18 float2 = 9x 16B loads each
        u64 fV[18], fS[18];
        {
            const ulonglong2* rp = reinterpret_cast<const ulonglong2*>(&vhV[r][c0]);
#pragma unroll
            for (int v = 0; v < 9; v++) { ulonglong2 t = rp[v]; fV[2*v] = t.x; fV[2*v+1] = t.y; }
        }
        {
            const ulonglong2* rp = reinterpret_cast<const ulonglong2*>(&vhS[r][c0]);
#pragma unroll
            for (int v = 0; v < 9; v++) { ulonglong2 t = rp[v]; fS[2*v] = t.x; fS[2*v+1] = t.y; }
        }
        float fC[20];
        {
            const float4* rp = reinterpret_cast<const float4*>(&vhC[r][c0]);
#pragma unroll
            for (int v = 0; v < 5; v++) {
                float4 t = rp[v];
                fC[4*v+0] = t.x; fC[4*v+1] = t.y; fC[4*v+2] = t.z; fC[4*v+3] = t.w;
            }
        }

        const float C1 = 1e-4f;
        const float C2 = 9e-4f;
#pragma unroll
        for (int i = 0; i < 8; i++) {
            // symmetric pair-sum form: 5 packed adds + 6 packed fmas per chain
            u64 mV, mS;
            float mC;
            {
                u64 accV = mul2(gw2[5], fV[i + 5]);
                u64 accS = mul2(gw2[5], fS[i + 5]);
                float accC = gw[5] * fC[i + 5];
#pragma unroll
                for (int d = 1; d <= 5; d++) {
                    const int ks = 5 - d;
                    u64 pv, ps;
                    {
                        float a0, a1, b0, b1;
                        unpack2(fV[i + 5 - d], a0, a1);
                        unpack2(fV[i + 5 + d], b0, b1);
                        pv = pack2(a0 + b0, a1 + b1);
                        unpack2(fS[i + 5 - d], a0, a1);
                        unpack2(fS[i + 5 + d], b0, b1);
                        ps = pack2(a0 + b0, a1 + b1);
                    }
                    accV = fma2(gw2[ks], pv, accV);
                    accS = fma2(gw2[ks], ps, accS);
                    accC += gw[ks] * (fC[i + 5 - d] + fC[i + 5 + d]);
                }
                mV = accV; mS = accS; mC = accC;
            }
            float mu1, mu2, vxx, vyy;
            unpack2(mV, mu1, mu2);
            unpack2(mS, vxx, vyy);
            const float mu1sq = mu1 * mu1;
            const float mu2sq = mu2 * mu2;
            const float mu12  = mu1 * mu2;
            const float s1  = vxx - mu1sq;
            const float s2  = vyy - mu2sq;
            const float s12 = mC  - mu12;
            const float num = (2.f * mu12 + C1) * (2.f * s12 + C2);
            const float den = (mu1sq + mu2sq + C1) * (s1 + s2 + C2 + 1e-6f);
            local += __fdividef(num, den);
        }
    }

    // ---------------- Reduction ----------------------------------------------
#pragma unroll
    for (int off = 16; off > 0; off >>= 1)
        local += __shfl_down_sync(0xffffffffu, local, off);
    if ((tid & 31) == 0) wpart[tid >> 5] = local;
    __syncthreads();
    if (tid == 0) {
        float bs = 0.f;
#pragma unroll
        for (int wv = 0; wv < NTH / 32; wv++) bs += wpart[wv];
        atomicAdd(&g_accum, (double)bs);
        __threadfence();
        const unsigned total = gridDim.x * gridDim.y * gridDim.z;
        if (atomicAdd(&g_count, 1u) == total - 1) {
            const double acc = atomicAdd(&g_accum, 0.0);
            out[0] = (float)(acc / ((double)PLANES * (double)W * (double)H));
            g_accum = 0.0;   // reset so every graph replay is identical
            g_count = 0u;
        }
    }
}

extern "C" void kernel_launch(void* const* d_in, const int* in_sizes, int n_in,
                              void* d_out, int out_size) {
    const float* img1 = (const float*)d_in[0];
    const float* img2 = (const float*)d_in[1];
    float* out = (float*)d_out;

    dim3 grid(W / TX, H / TY, PLANES);
    ssim_fused<<<grid, NTH>>>(img1, img2, out);
}

// round 5
// speedup vs baseline: 2.1865x; 1.0200x over previous
#include <cuda_runtime.h>

#define W 512
#define H 512
#define PLANES 48
#define TX 64          // output tile width
#define TY 32          // output tile height
#define HALO 5
#define NCOL 74        // TX + 2*HALO columns of intermediates
#define PSTRIDE 74     // float2 stride (148 words ≡ 20 mod 32 -> conflict-free 16B loads)
#define CSTRIDE 76     // float stride  (76 ≡ 12 mod 32 -> conflict-free 16B loads)
#define NTH 320

typedef unsigned long long u64;

__device__ double g_accum;
__device__ unsigned int g_count;

// Gaussian taps exp(-d^2/4.5), normalized in double at compile time.
#define E0d 1.0
#define E1d 0.8007374029168081
#define E2d 0.4111122905071874
#define E3d 0.1353352832366127
#define E4d 0.0285655007845531
#define E5d 0.0038659201394728
#define ESd (E0d + 2.0*(E1d+E2d+E3d+E4d+E5d))
#define GW0 ((float)(E5d/ESd))
#define GW1 ((float)(E4d/ESd))
#define GW2 ((float)(E3d/ESd))
#define GW3 ((float)(E2d/ESd))
#define GW4 ((float)(E1d/ESd))
#define GW5 ((float)(E0d/ESd))

__device__ __forceinline__ u64 pack2(float a, float b) {
    u64 r; asm("mov.b64 %0, {%1, %2};" : "=l"(r) : "f"(a), "f"(b)); return r;
}
__device__ __forceinline__ void unpack2(u64 v, float& a, float& b) {
    asm("mov.b64 {%0, %1}, %2;" : "=f"(a), "=f"(b) : "l"(v));
}
__device__ __forceinline__ u64 fma2(u64 a, u64 b, u64 c) {
    u64 d; asm("fma.rn.f32x2 %0, %1, %2, %3;" : "=l"(d) : "l"(a), "l"(b), "l"(c)); return d;
}
__device__ __forceinline__ u64 mul2(u64 a, u64 b) {
    u64 d; asm("mul.rn.f32x2 %0, %1, %2;" : "=l"(d) : "l"(a), "l"(b)); return d;
}

// Vertical pass: one column strip per thread, 8 output rows from 18 input
// rows, all in registers. Packed (x,y) and (x2,y2) chains + scalar xy.
template<bool GUARD>
__device__ __forceinline__ void phaseA(const float* __restrict__ p1,
                                       const float* __restrict__ p2,
                                       int row0, int col0, int tid,
                                       u64 (*vhV)[PSTRIDE], u64 (*vhS)[PSTRIDE],
                                       float (*vhC)[CSTRIDE],
                                       const float* gw, const u64* gw2) {
    const int gi = tid / NCOL;          // row group 0..3
    const int cc = tid - gi * NCOL;     // column 0..73
    const int gc = col0 + cc - HALO;
    const int rbase = row0 + gi * 8 - HALO;
    const bool colOk = !GUARD || ((unsigned)gc < (unsigned)W);

    u64 aV[8], aS[8];
    float aC[8];
#pragma unroll
    for (int i = 0; i < 8; i++) { aV[i] = 0ull; aS[i] = 0ull; aC[i] = 0.f; }

#pragma unroll
    for (int j = 0; j < 18; j++) {
        const int gr = rbase + j;
        float x = 0.f, y = 0.f;
        if (!GUARD || (colOk && (unsigned)gr < (unsigned)H)) {
            const int off = gr * W + gc;
            x = p1[off];
            y = p2[off];
        }
        const u64 v  = pack2(x, y);
        const u64 sq = mul2(v, v);
        const float cr = x * y;
#pragma unroll
        for (int i = 0; i < 8; i++) {
            const int k = j - i;        // compile-time tap index
            if (k >= 0 && k < 11) {
                const int ks = (k < 10 - k) ? k : (10 - k);  // symmetric tap
                aV[i] = fma2(gw2[ks], v,  aV[i]);
                aS[i] = fma2(gw2[ks], sq, aS[i]);
                aC[i] += gw[ks] * cr;
            }
        }
    }
    const int r0 = gi * 8;
#pragma unroll
    for (int i = 0; i < 8; i++) {
        vhV[r0 + i][cc] = aV[i];
        vhS[r0 + i][cc] = aS[i];
        vhC[r0 + i][cc] = aC[i];
    }
}

__launch_bounds__(NTH, 3)
__global__ void ssim_fused(const float* __restrict__ img1,
                           const float* __restrict__ img2,
                           float* __restrict__ out) {
    __shared__ __align__(16) u64   vhV[TY][PSTRIDE];   // (hx, hy)    18944 B
    __shared__ __align__(16) u64   vhS[TY][PSTRIDE];   // (hxx, hyy)  18944 B
    __shared__ __align__(16) float vhC[TY][CSTRIDE];   // hxy          9728 B
    __shared__ float wpart[NTH / 32];

    // only 6 distinct taps kept live (symmetry)
    const float gw[6] = {GW0, GW1, GW2, GW3, GW4, GW5};
    u64 gw2[6];
#pragma unroll
    for (int k = 0; k < 6; k++) gw2[k] = pack2(gw[k], gw[k]);

    const int tid   = threadIdx.x;
    const int plane = blockIdx.z;
    const int row0  = blockIdx.y * TY;
    const int col0  = blockIdx.x * TX;
    const float* p1 = img1 + (size_t)plane * (W * H);
    const float* p2 = img2 + (size_t)plane * (W * H);

    // ---------------- Phase A: vertical pass --------------------------------
    if (tid < 4 * NCOL) {
        const bool interior = (row0 >= HALO) && (row0 + TY + HALO <= H) &&
                              (col0 >= HALO) && (col0 + TX + HALO <= W);
        if (interior)
            phaseA<false>(p1, p2, row0, col0, tid, vhV, vhS, vhC, gw, gw2);
        else
            phaseA<true >(p1, p2, row0, col0, tid, vhV, vhS, vhC, gw, gw2);
    }
    __syncthreads();

    // ---------------- Phase B: horizontal pass + SSIM -----------------------
    float local = 0.f;
    if (tid < 256) {
        const int r  = tid & 31;
        const int c0 = (tid >> 5) * 8;   // output col group (even -> 16B aligned)

        // packed windows: 18 float2 = 9x 16B loads each
        u64 fV[18], fS[18];
        {
            const ulonglong2* rp = reinterpret_cast<const ulonglong2*>(&vhV[r][c0]);
#pragma unroll
            for (int v = 0; v < 9; v++) { ulonglong2 t = rp[v]; fV[2*v] = t.x; fV[2*v+1] = t.y; }
        }
        {
            const ulonglong2* rp = reinterpret_cast<const ulonglong2*>(&vhS[r][c0]);
#pragma unroll
            for (int v = 0; v < 9; v++) { ulonglong2 t = rp[v]; fS[2*v] = t.x; fS[2*v+1] = t.y; }
        }
        float fC[20];
        {
            const float4* rp = reinterpret_cast<const float4*>(&vhC[r][c0]);
#pragma unroll
            for (int v = 0; v < 5; v++) {
                float4 t = rp[v];
                fC[4*v+0] = t.x; fC[4*v+1] = t.y; fC[4*v+2] = t.z; fC[4*v+3] = t.w;
            }
        }

        const float C1 = 1e-4f;
        const float C2 = 9e-4f;
#pragma unroll
        for (int i = 0; i < 8; i++) {
            // straight 11-tap chains; symmetric weight indexing (6 live weights)
            u64 mV = 0ull, mS = 0ull;
            float mC = 0.f;
#pragma unroll
            for (int k = 0; k < 11; k++) {
                const int ks = (k < 10 - k) ? k : (10 - k);
                mV = fma2(gw2[ks], fV[i + k], mV);
                mS = fma2(gw2[ks], fS[i + k], mS);
                mC += gw[ks] * fC[i + k];
            }
            float mu1, mu2, vxx, vyy;
            unpack2(mV, mu1, mu2);
            unpack2(mS, vxx, vyy);
            const float mu1sq = mu1 * mu1;
            const float mu2sq = mu2 * mu2;
            const float mu12  = mu1 * mu2;
            const float s1  = vxx - mu1sq;
            const float s2  = vyy - mu2sq;
            const float s12 = mC  - mu12;
            const float num = (2.f * mu12 + C1) * (2.f * s12 + C2);
            const float den = (mu1sq + mu2sq + C1) * (s1 + s2 + C2 + 1e-6f);
            local += __fdividef(num, den);
        }
    }

    // ---------------- Reduction ----------------------------------------------
#pragma unroll
    for (int off = 16; off > 0; off >>= 1)
        local += __shfl_down_sync(0xffffffffu, local, off);
    if ((tid & 31) == 0) wpart[tid >> 5] = local;
    __syncthreads();
    if (tid == 0) {
        float bs = 0.f;
#pragma unroll
        for (int wv = 0; wv < NTH / 32; wv++) bs += wpart[wv];
        atomicAdd(&g_accum, (double)bs);
        __threadfence();
        const unsigned total = gridDim.x * gridDim.y * gridDim.z;
        if (atomicAdd(&g_count, 1u) == total - 1) {
            const double acc = atomicAdd(&g_accum, 0.0);
            out[0] = (float)(acc / ((double)PLANES * (double)W * (double)H));
            g_accum = 0.0;   // reset so every graph replay is identical
            g_count = 0u;
        }
    }
}

extern "C" void kernel_launch(void* const* d_in, const int* in_sizes, int n_in,
                              void* d_out, int out_size) {
    const float* img1 = (const float*)d_in[0];
    const float* img2 = (const float*)d_in[1];
    float* out = (float*)d_out;

    dim3 grid(W / TX, H / TY, PLANES);
    ssim_fused<<<grid, NTH>>>(img1, img2, out);
}